// round 1
// baseline (speedup 1.0000x reference)
#include <cuda_runtime.h>
#include <math.h>

// ---------------- problem constants ----------------
#define BTT   40          // B*T
#define NTOK  199
#define DIMD  768
#define DEPTH 12
#define HEADS 12
#define DHD   64
#define MLPD  3072
#define NPATCH 196
#define ROWS  (BTT*NTOK)    // 7960
#define PROWS (BTT*NPATCH)  // 7840

// ---------------- scratch (device globals, no allocs) ----------------
__device__ float g_x  [ROWS*DIMD];
__device__ float g_h  [ROWS*DIMD];
__device__ float g_o  [ROWS*DIMD];
__device__ float g_qkv[ROWS*3*DIMD];
__device__ float g_ff [ROWS*MLPD];
__device__ float g_pv [PROWS*DIMD];
__device__ float g_pe [PROWS*DIMD];
__device__ float g_wt [DIMD*DIMD];

// ---------------- helpers ----------------
__device__ __forceinline__ float gelu_f(float v) {
    return 0.5f * v * (1.0f + erff(v * 0.70710678118654752f));
}

// ---------------- SGEMM: C = A(MxK) * B(KxN), epilogues ----------------
// MODE 0: plain; 1: +bias; 2: +bias +residual; 3: gelu(+bias)
template<int MODE>
__global__ __launch_bounds__(256)
void sgemm(const float* __restrict__ A, const float* __restrict__ B,
           const float* __restrict__ bias, const float* __restrict__ res,
           float* __restrict__ C, int M, int N, int K)
{
    __shared__ float As[8][128];
    __shared__ float Bs[8][128];
    int tid = threadIdx.x;
    int bm = blockIdx.y * 128, bn = blockIdx.x * 128;
    int arow = tid >> 1, acol = (tid & 1) * 4;
    int brow = tid >> 5, bcol = (tid & 31) * 4;
    int tx = tid & 15, ty = tid >> 4;

    float acc[8][8];
    #pragma unroll
    for (int i = 0; i < 8; i++)
        #pragma unroll
        for (int j = 0; j < 8; j++) acc[i][j] = 0.f;

    bool aval = (bm + arow) < M;
    const float* Aptr = A + (size_t)(bm + arow) * K + acol;
    const float* Bptr = B + (size_t)brow * N + bn + bcol;

    for (int k0 = 0; k0 < K; k0 += 8) {
        float4 av = aval ? *(const float4*)(Aptr + k0) : make_float4(0.f,0.f,0.f,0.f);
        As[acol+0][arow] = av.x; As[acol+1][arow] = av.y;
        As[acol+2][arow] = av.z; As[acol+3][arow] = av.w;
        *(float4*)&Bs[brow][bcol] = *(const float4*)(Bptr + (size_t)k0 * N);
        __syncthreads();
        #pragma unroll
        for (int kk = 0; kk < 8; kk++) {
            float ar[8], br[8];
            *(float4*)(ar)   = *(const float4*)&As[kk][ty*8];
            *(float4*)(ar+4) = *(const float4*)&As[kk][ty*8+4];
            *(float4*)(br)   = *(const float4*)&Bs[kk][tx*8];
            *(float4*)(br+4) = *(const float4*)&Bs[kk][tx*8+4];
            #pragma unroll
            for (int i = 0; i < 8; i++)
                #pragma unroll
                for (int j = 0; j < 8; j++)
                    acc[i][j] = fmaf(ar[i], br[j], acc[i][j]);
        }
        __syncthreads();
    }

    #pragma unroll
    for (int i = 0; i < 8; i++) {
        int row = bm + ty*8 + i;
        if (row >= M) continue;
        float* crow = C + (size_t)row * N + bn + tx*8;
        const float* rrow = (MODE == 2) ? (res + (size_t)row * N + bn + tx*8) : nullptr;
        #pragma unroll
        for (int j = 0; j < 8; j++) {
            float v = acc[i][j];
            if (MODE >= 1) v += bias[bn + tx*8 + j];
            if (MODE == 3) v = gelu_f(v);
            if (MODE == 2) v += rrow[j];
            crow[j] = v;
        }
    }
}

// ---------------- LayerNorm (one block per row) ----------------
__global__ __launch_bounds__(256)
void ln_kernel(const float* __restrict__ x, const float* __restrict__ s,
               const float* __restrict__ b, float* __restrict__ y)
{
    int row = blockIdx.x;
    const float* xr = x + (size_t)row * DIMD;
    int tid = threadIdx.x;
    __shared__ float red[256];
    float v0 = xr[tid], v1 = xr[tid+256], v2 = xr[tid+512];
    red[tid] = v0 + v1 + v2;
    __syncthreads();
    for (int o = 128; o > 0; o >>= 1) { if (tid < o) red[tid] += red[tid+o]; __syncthreads(); }
    float mean = red[0] * (1.f/768.f);
    __syncthreads();
    float d0 = v0-mean, d1 = v1-mean, d2 = v2-mean;
    red[tid] = d0*d0 + d1*d1 + d2*d2;
    __syncthreads();
    for (int o = 128; o > 0; o >>= 1) { if (tid < o) red[tid] += red[tid+o]; __syncthreads(); }
    float inv = rsqrtf(red[0] * (1.f/768.f) + 1e-5f);
    float* yr = y + (size_t)row * DIMD;
    yr[tid]     = d0*inv*s[tid]     + b[tid];
    yr[tid+256] = d1*inv*s[tid+256] + b[tid+256];
    yr[tid+512] = d2*inv*s[tid+512] + b[tid+512];
}

// ---------------- fused attention: one block per (seq, head) ----------------
// smem: Ks[224][65] (zero padded rows), Vs[199][64], q per warp [8][64], scores [8][200]
#define SMEM_ATTN ((224*65 + 199*64 + 8*64 + 8*200) * 4)
__global__ __launch_bounds__(256)
void attn_kernel(const float* __restrict__ qkv, float* __restrict__ o)
{
    extern __shared__ float sm[];
    float* Ks  = sm;                 // 224*65
    float* Vs  = Ks + 224*65;        // 199*64
    float* qsh = Vs + 199*64;        // 8*64
    float* ssh = qsh + 8*64;         // 8*200

    int bt = blockIdx.x / HEADS;
    int hh = blockIdx.x % HEADS;
    const float* base = qkv + (size_t)bt * NTOK * (3*DIMD) + hh * DHD;
    int tid = threadIdx.x;

    for (int idx = tid; idx < 224*64; idx += 256) {
        int j = idx >> 6, d = idx & 63;
        float kv = 0.f;
        if (j < NTOK) {
            kv = base[(size_t)j*(3*DIMD) + DIMD + d];
            Vs[j*64 + d] = base[(size_t)j*(3*DIMD) + 2*DIMD + d];
        }
        Ks[j*65 + d] = kv;
    }
    __syncthreads();

    int w = tid >> 5, lane = tid & 31;
    float* qw = qsh + w*64;
    float* sw = ssh + w*200;

    for (int i = w; i < NTOK; i += 8) {
        const float* qrow = base + (size_t)i * (3*DIMD);
        qw[lane]      = qrow[lane];
        qw[lane + 32] = qrow[lane + 32];
        __syncwarp();

        float acc[7] = {0.f,0.f,0.f,0.f,0.f,0.f,0.f};
        #pragma unroll 4
        for (int d = 0; d < 64; d++) {
            float qd = qw[d];
            #pragma unroll
            for (int r = 0; r < 7; r++)
                acc[r] = fmaf(qd, Ks[(lane + 32*r)*65 + d], acc[r]);
        }
        float mx = -1e30f;
        #pragma unroll
        for (int r = 0; r < 7; r++) {
            acc[r] *= 0.125f;  // 1/sqrt(64)
            if (lane + 32*r < NTOK) mx = fmaxf(mx, acc[r]);
        }
        for (int off = 16; off; off >>= 1)
            mx = fmaxf(mx, __shfl_xor_sync(0xffffffffu, mx, off));
        float sum = 0.f, p[7];
        #pragma unroll
        for (int r = 0; r < 7; r++) {
            int j = lane + 32*r;
            p[r] = (j < NTOK) ? __expf(acc[r] - mx) : 0.f;
            sum += p[r];
        }
        for (int off = 16; off; off >>= 1)
            sum += __shfl_xor_sync(0xffffffffu, sum, off);
        float rinv = 1.f / sum;
        #pragma unroll
        for (int r = 0; r < 7; r++) {
            int j = lane + 32*r;
            if (j < NTOK) sw[j] = p[r] * rinv;
        }
        __syncwarp();

        float o0 = 0.f, o1 = 0.f;
        for (int j = 0; j < NTOK; j++) {
            float s = sw[j];
            o0 = fmaf(s, Vs[j*64 + lane],      o0);
            o1 = fmaf(s, Vs[j*64 + lane + 32], o1);
        }
        o[((size_t)bt*NTOK + i)*DIMD + hh*DHD + lane]      = o0;
        o[((size_t)bt*NTOK + i)*DIMD + hh*DHD + lane + 32] = o1;
        __syncwarp();
    }
}

// ---------------- patch embed pieces ----------------
__global__ void transpose_kernel(const float* __restrict__ w, float* __restrict__ wt)
{
    __shared__ float tile[16][17];
    int x = blockIdx.x*16 + threadIdx.x;
    int y = blockIdx.y*16 + threadIdx.y;
    tile[threadIdx.y][threadIdx.x] = w[y*DIMD + x];
    __syncthreads();
    int xo = blockIdx.y*16 + threadIdx.x;
    int yo = blockIdx.x*16 + threadIdx.y;
    wt[yo*DIMD + xo] = tile[threadIdx.x][threadIdx.y];
}

__global__ void im2col_kernel(const float* __restrict__ img, float* __restrict__ pv)
{
    int idx = blockIdx.x*256 + threadIdx.x;
    if (idx >= PROWS*DIMD) return;
    int k   = idx % DIMD;
    int row = idx / DIMD;
    int bt = row / NPATCH, p = row % NPATCH;
    int c = k >> 8, rem = k & 255, ii = rem >> 4, jj = rem & 15;
    int ph = p / 14, pw = p % 14;
    pv[idx] = img[(((size_t)bt*3 + c)*224 + ph*16 + ii)*224 + pw*16 + jj];
}

__global__ void assemble_kernel(const float* __restrict__ pe, const float* __restrict__ face,
                                const float* __restrict__ pos, const float* __restrict__ time_emb,
                                const float* __restrict__ cls, float* __restrict__ x)
{
    int idx = blockIdx.x*256 + threadIdx.x;
    if (idx >= ROWS*DIMD) return;
    int n   = idx % DIMD;
    int rem = idx / DIMD;
    int tok = rem % NTOK;
    int bt  = rem / NTOK;
    int t   = bt % 20;
    float v;
    if (tok == 0)          v = cls[n] + pos[n];
    else if (tok <= NPATCH) v = pe[((size_t)bt*NPATCH + tok-1)*DIMD + n] + pos[tok*DIMD + n];
    else                   v = face[((size_t)bt*2 + (tok-197))*DIMD + n];
    x[idx] = v + time_emb[t*DIMD + n];
}

// ---------------- output extraction ----------------
#define OUT_TOT (3*BTT*DIMD + BTT*NPATCH*DIMD)
__global__ void extract_kernel(const float* __restrict__ x, float* __restrict__ out)
{
    int idx = blockIdx.x*256 + threadIdx.x;
    const int P = BTT*DIMD;
    if (idx >= OUT_TOT) return;
    if (idx < 3*P) {
        int part = idx / P;
        int r = idx % P;
        int bt = r / DIMD, n = r % DIMD;
        int tok = (part == 0) ? 0 : (part == 1 ? 197 : 198);
        out[idx] = x[((size_t)bt*NTOK + tok)*DIMD + n];
    } else {
        int r = idx - 3*P;
        int n  = r % DIMD;
        int pp = (r / DIMD) % NPATCH;
        int bt = r / (DIMD*NPATCH);
        out[idx] = x[((size_t)bt*NTOK + 1 + pp)*DIMD + n];
    }
}

// ---------------- host-side launcher ----------------
static void launch_gemm(int mode, const float* A, const float* B, const float* bias,
                        const float* res, float* C, int M, int N, int K)
{
    dim3 grid(N/128, (M + 127)/128);
    dim3 blk(256);
    switch (mode) {
        case 0: sgemm<0><<<grid, blk>>>(A, B, bias, res, C, M, N, K); break;
        case 1: sgemm<1><<<grid, blk>>>(A, B, bias, res, C, M, N, K); break;
        case 2: sgemm<2><<<grid, blk>>>(A, B, bias, res, C, M, N, K); break;
        case 3: sgemm<3><<<grid, blk>>>(A, B, bias, res, C, M, N, K); break;
    }
}

extern "C" void kernel_launch(void* const* d_in, const int* in_sizes, int n_in,
                              void* d_out, int out_size)
{
    (void)in_sizes; (void)n_in; (void)out_size;
    const float* img      = (const float*)d_in[0];
    const float* face     = (const float*)d_in[1];
    const float* conv_w   = (const float*)d_in[2];
    const float* conv_b   = (const float*)d_in[3];
    const float* pos_emb  = (const float*)d_in[4];
    const float* time_emb = (const float*)d_in[5];
    const float* cls_tok  = (const float*)d_in[6];
    const float* ln1_s    = (const float*)d_in[7];
    const float* ln1_b    = (const float*)d_in[8];
    const float* qkv_w    = (const float*)d_in[9];
    const float* out_w    = (const float*)d_in[10];
    const float* out_b    = (const float*)d_in[11];
    const float* ln2_s    = (const float*)d_in[12];
    const float* ln2_b    = (const float*)d_in[13];
    const float* ff_w1    = (const float*)d_in[14];
    const float* ff_b1    = (const float*)d_in[15];
    const float* ff_w2    = (const float*)d_in[16];
    const float* ff_b2    = (const float*)d_in[17];
    float* out = (float*)d_out;

    float *gx, *gh, *go, *gqkv, *gff, *gpv, *gpe, *gwt;
    cudaGetSymbolAddress((void**)&gx,   g_x);
    cudaGetSymbolAddress((void**)&gh,   g_h);
    cudaGetSymbolAddress((void**)&go,   g_o);
    cudaGetSymbolAddress((void**)&gqkv, g_qkv);
    cudaGetSymbolAddress((void**)&gff,  g_ff);
    cudaGetSymbolAddress((void**)&gpv,  g_pv);
    cudaGetSymbolAddress((void**)&gpe,  g_pe);
    cudaGetSymbolAddress((void**)&gwt,  g_wt);

    cudaFuncSetAttribute(attn_kernel, cudaFuncAttributeMaxDynamicSharedMemorySize, SMEM_ATTN);

    // ---- patch embed ----
    transpose_kernel<<<dim3(DIMD/16, DIMD/16), dim3(16,16)>>>(conv_w, gwt);
    im2col_kernel<<<(PROWS*DIMD + 255)/256, 256>>>(img, gpv);
    launch_gemm(1, gpv, gwt, conv_b, nullptr, gpe, PROWS, DIMD, DIMD);
    assemble_kernel<<<(ROWS*DIMD + 255)/256, 256>>>(gpe, face, pos_emb, time_emb, cls_tok, gx);

    // ---- transformer layers ----
    for (int l = 0; l < DEPTH; l++) {
        ln_kernel<<<ROWS, 256>>>(gx, ln1_s + l*DIMD, ln1_b + l*DIMD, gh);
        launch_gemm(0, gh, qkv_w + (size_t)l*DIMD*3*DIMD, nullptr, nullptr,
                    gqkv, ROWS, 3*DIMD, DIMD);
        attn_kernel<<<BTT*HEADS, 256, SMEM_ATTN>>>(gqkv, go);
        launch_gemm(2, go, out_w + (size_t)l*DIMD*DIMD, out_b + l*DIMD, gx,
                    gx, ROWS, DIMD, DIMD);
        ln_kernel<<<ROWS, 256>>>(gx, ln2_s + l*DIMD, ln2_b + l*DIMD, gh);
        launch_gemm(3, gh, ff_w1 + (size_t)l*DIMD*MLPD, ff_b1 + l*MLPD, nullptr,
                    gff, ROWS, MLPD, DIMD);
        launch_gemm(2, gff, ff_w2 + (size_t)l*MLPD*DIMD, ff_b2 + l*DIMD, gx,
                    gx, ROWS, DIMD, MLPD);
    }

    // ---- outputs ----
    extract_kernel<<<(OUT_TOT + 255)/256, 256>>>(gx, out);
}

// round 3
// speedup vs baseline: 4.0047x; 4.0047x over previous
#include <cuda_runtime.h>
#include <cuda_fp16.h>
#include <math.h>
#include <stdint.h>

// ---------------- problem constants ----------------
#define BTT   40
#define NTOK  199
#define DIMD  768
#define DEPTH 12
#define HEADS 12
#define DHD   64
#define MLPD  3072
#define NPATCH 196
#define ROWS  (BTT*NTOK)    // 7960
#define PROWS (BTT*NPATCH)  // 7840
#define MPAD  8064          // 63*128 — all fp16 A-side buffers padded to this

// ---------------- scratch (device globals) ----------------
__device__ float  g_x  [ROWS*DIMD];
__device__ float  g_qkv[ROWS*3*DIMD];
__device__ float  g_pe [PROWS*DIMD];
__device__ __half g_ah [MPAD*DIMD];      // LN out / im2col
__device__ __half g_oh [MPAD*DIMD];      // attention out
__device__ __half g_ffh[MPAD*MLPD];      // gelu out
__device__ __half g_wc  [DIMD*DIMD];
__device__ __half g_wqkv[DEPTH*3*DIMD*DIMD];
__device__ __half g_wo  [DEPTH*DIMD*DIMD];
__device__ __half g_w1  [DEPTH*MLPD*DIMD];
__device__ __half g_w2  [DEPTH*DIMD*MLPD];

// ---------------- helpers ----------------
__device__ __forceinline__ uint32_t smem_u32(const void* p) {
    uint32_t a;
    asm("{ .reg .u64 t; cvta.to.shared.u64 t, %1; cvt.u32.u64 %0, t; }" : "=r"(a) : "l"(p));
    return a;
}
__device__ __forceinline__ float gelu_f(float v) {
    return 0.5f * v * (1.0f + erff(v * 0.70710678118654752f));
}

#define CP16(dst, src)  asm volatile("cp.async.ca.shared.global [%0], [%1], 16;" :: "r"(dst), "l"(src))
#define CP_COMMIT()     asm volatile("cp.async.commit_group;" ::: "memory")
#define CP_WAIT(n)      asm volatile("cp.async.wait_group %0;" :: "n"(n) : "memory")

__device__ __forceinline__ void ldsm4(uint32_t* r, uint32_t a) {
    asm volatile("ldmatrix.sync.aligned.m8n8.x4.shared.b16 {%0,%1,%2,%3}, [%4];"
                 : "=r"(r[0]), "=r"(r[1]), "=r"(r[2]), "=r"(r[3]) : "r"(a));
}
__device__ __forceinline__ void mma16816(float* c, const uint32_t* a, const uint32_t* b) {
    asm volatile("mma.sync.aligned.m16n8k16.row.col.f32.f16.f16.f32 "
                 "{%0,%1,%2,%3}, {%4,%5,%6,%7}, {%8,%9}, {%0,%1,%2,%3};"
                 : "+f"(c[0]), "+f"(c[1]), "+f"(c[2]), "+f"(c[3])
                 : "r"(a[0]), "r"(a[1]), "r"(a[2]), "r"(a[3]), "r"(b[0]), "r"(b[1]));
}

// ---------------- HMMA fp16 GEMM: C(MxN) = A(MxK) * B[N][K]^T ----------------
// A rows padded (reads up to gridM*128 rows — buffers are MPAD rows). N%128==0, K%32==0.
// MODE 0: plain fp32 C; 1: +bias fp32; 2: +bias+residual fp32; 3: gelu(+bias) -> fp16 Ch
#define ROWB 80                       // padded smem row bytes (32 halves + 8 pad)
#define TILEB (128*ROWB)              // 10240 B per operand tile
#define GEMM_SMEM (3*2*TILEB)         // 61440 B (3 stages, A+B)

template<int MODE>
__global__ __launch_bounds__(256, 2)
void hgemm(const __half* __restrict__ A, const __half* __restrict__ Bw,
           const float* __restrict__ bias, const float* __restrict__ res,
           float* __restrict__ C, __half* __restrict__ Ch,
           int M, int N, int K)
{
    extern __shared__ char smem[];
    uint32_t sb = smem_u32(smem);
    int tid = threadIdx.x, lane = tid & 31, wid = tid >> 5;
    int wm = wid & 1, wn = wid >> 1;          // warp grid 2(M) x 4(N)
    int bm = blockIdx.y * 128, bn = blockIdx.x * 128;

    const __half* Ag = A + (size_t)bm * K;
    const __half* Bg = Bw + (size_t)bn * K;
    const int T = K >> 5;

    // per-thread cp.async chunks: 2 per operand per stage
    int r0 = tid >> 1;                  // not used; use id mapping below
    (void)r0;

    float acc[4][4][4];
    #pragma unroll
    for (int i = 0; i < 4; i++)
        #pragma unroll
        for (int j = 0; j < 4; j++)
            #pragma unroll
            for (int q = 0; q < 4; q++) acc[i][j][q] = 0.f;

    // ---- load one k-tile into stage s ----
    auto load_tile = [&](int s, int t) {
        uint32_t abase = sb + s * 2 * TILEB;
        uint32_t bbase = abase + TILEB;
        const __half* Agt = Ag + t * 32;
        const __half* Bgt = Bg + t * 32;
        #pragma unroll
        for (int i = 0; i < 2; i++) {
            int id = tid + i * 256;
            int r = id >> 2, c = id & 3;
            CP16(abase + r * ROWB + c * 16, Agt + (size_t)r * K + c * 8);
            CP16(bbase + r * ROWB + c * 16, Bgt + (size_t)r * K + c * 8);
        }
    };

    load_tile(0, 0); CP_COMMIT();
    if (T > 1) { load_tile(1, 1); CP_COMMIT(); }

    // ldmatrix source addresses (relative to stage base)
    uint32_t a_off = (uint32_t)((wm * 64 + (lane & 15)) * ROWB + ((lane >> 4) * 8) * 2);
    uint32_t b_off = (uint32_t)((wn * 32 + (lane & 7) + ((lane >> 4) & 1) * 8) * ROWB
                                + (((lane >> 3) & 1) * 8) * 2);

    for (int t = 0; t < T; t++) {
        if (t == T - 1) { CP_WAIT(0); } else { CP_WAIT(1); }
        __syncthreads();
        int buf = t % 3;
        if (t + 2 < T) { load_tile((t + 2) % 3, t + 2); CP_COMMIT(); }

        uint32_t abase = sb + buf * 2 * TILEB;
        uint32_t bbase = abase + TILEB;
        #pragma unroll
        for (int kk = 0; kk < 2; kk++) {
            uint32_t af[4][4], bf[4][2];
            #pragma unroll
            for (int mi = 0; mi < 4; mi++)
                ldsm4(af[mi], abase + a_off + mi * 16 * ROWB + kk * 32);
            #pragma unroll
            for (int ng = 0; ng < 2; ng++) {
                uint32_t r[4];
                ldsm4(r, bbase + b_off + ng * 16 * ROWB + kk * 32);
                bf[2*ng][0]   = r[0]; bf[2*ng][1]   = r[1];
                bf[2*ng+1][0] = r[2]; bf[2*ng+1][1] = r[3];
            }
            #pragma unroll
            for (int mi = 0; mi < 4; mi++)
                #pragma unroll
                for (int ni = 0; ni < 4; ni++)
                    mma16816(acc[mi][ni], af[mi], bf[ni]);
        }
    }

    // ---- epilogue ----
    int lrow = lane >> 2, lcol = (lane & 3) * 2;
    #pragma unroll
    for (int mi = 0; mi < 4; mi++) {
        #pragma unroll
        for (int h = 0; h < 2; h++) {
            int row = bm + wm * 64 + mi * 16 + lrow + h * 8;
            if (row >= M) continue;
            #pragma unroll
            for (int ni = 0; ni < 4; ni++) {
                int col = bn + wn * 32 + ni * 8 + lcol;
                float v0 = acc[mi][ni][2*h + 0];
                float v1 = acc[mi][ni][2*h + 1];
                if (MODE >= 1) { v0 += bias[col]; v1 += bias[col + 1]; }
                if (MODE == 3) {
                    v0 = gelu_f(v0); v1 = gelu_f(v1);
                    __half2 h2 = __floats2half2_rn(v0, v1);
                    *(__half2*)(Ch + (size_t)row * N + col) = h2;
                } else {
                    if (MODE == 2) {
                        const float2 rr = *(const float2*)(res + (size_t)row * N + col);
                        v0 += rr.x; v1 += rr.y;
                    }
                    *(float2*)(C + (size_t)row * N + col) = make_float2(v0, v1);
                }
            }
        }
    }
}

// ---------------- LayerNorm: fp32 in -> fp16 out ----------------
__global__ __launch_bounds__(256)
void ln_kernel(const float* __restrict__ x, const float* __restrict__ s,
               const float* __restrict__ b, __half* __restrict__ y)
{
    int row = blockIdx.x;
    const float* xr = x + (size_t)row * DIMD;
    int tid = threadIdx.x;
    __shared__ float red[256];
    float v0 = xr[tid], v1 = xr[tid+256], v2 = xr[tid+512];
    red[tid] = v0 + v1 + v2;
    __syncthreads();
    for (int o = 128; o > 0; o >>= 1) { if (tid < o) red[tid] += red[tid+o]; __syncthreads(); }
    float mean = red[0] * (1.f/768.f);
    __syncthreads();
    float d0 = v0-mean, d1 = v1-mean, d2 = v2-mean;
    red[tid] = d0*d0 + d1*d1 + d2*d2;
    __syncthreads();
    for (int o = 128; o > 0; o >>= 1) { if (tid < o) red[tid] += red[tid+o]; __syncthreads(); }
    float inv = rsqrtf(red[0] * (1.f/768.f) + 1e-5f);
    __half* yr = y + (size_t)row * DIMD;
    yr[tid]     = __float2half(d0*inv*s[tid]     + b[tid]);
    yr[tid+256] = __float2half(d1*inv*s[tid+256] + b[tid+256]);
    yr[tid+512] = __float2half(d2*inv*s[tid+512] + b[tid+512]);
}

// ---------------- fused attention (fp32 compute, fp16 out) ----------------
#define SMEM_ATTN ((224*65 + 199*64 + 8*64 + 8*200) * 4)
__global__ __launch_bounds__(256)
void attn_kernel(const float* __restrict__ qkv, __half* __restrict__ o)
{
    extern __shared__ float sm[];
    float* Ks  = sm;
    float* Vs  = Ks + 224*65;
    float* qsh = Vs + 199*64;
    float* ssh = qsh + 8*64;

    int bt = blockIdx.x / HEADS;
    int hh = blockIdx.x % HEADS;
    const float* base = qkv + (size_t)bt * NTOK * (3*DIMD) + hh * DHD;
    int tid = threadIdx.x;

    for (int idx = tid; idx < 224*64; idx += 256) {
        int j = idx >> 6, d = idx & 63;
        float kv = 0.f;
        if (j < NTOK) {
            kv = base[(size_t)j*(3*DIMD) + DIMD + d];
            Vs[j*64 + d] = base[(size_t)j*(3*DIMD) + 2*DIMD + d];
        }
        Ks[j*65 + d] = kv;
    }
    __syncthreads();

    int w = tid >> 5, lane = tid & 31;
    float* qw = qsh + w*64;
    float* sw = ssh + w*200;

    for (int i = w; i < NTOK; i += 8) {
        const float* qrow = base + (size_t)i * (3*DIMD);
        qw[lane]      = qrow[lane];
        qw[lane + 32] = qrow[lane + 32];
        __syncwarp();

        float acc[7] = {0.f,0.f,0.f,0.f,0.f,0.f,0.f};
        #pragma unroll 4
        for (int d = 0; d < 64; d++) {
            float qd = qw[d];
            #pragma unroll
            for (int r = 0; r < 7; r++)
                acc[r] = fmaf(qd, Ks[(lane + 32*r)*65 + d], acc[r]);
        }
        float mx = -1e30f;
        #pragma unroll
        for (int r = 0; r < 7; r++) {
            acc[r] *= 0.125f;
            if (lane + 32*r < NTOK) mx = fmaxf(mx, acc[r]);
        }
        for (int off = 16; off; off >>= 1)
            mx = fmaxf(mx, __shfl_xor_sync(0xffffffffu, mx, off));
        float sum = 0.f, p[7];
        #pragma unroll
        for (int r = 0; r < 7; r++) {
            int j = lane + 32*r;
            p[r] = (j < NTOK) ? __expf(acc[r] - mx) : 0.f;
            sum += p[r];
        }
        for (int off = 16; off; off >>= 1)
            sum += __shfl_xor_sync(0xffffffffu, sum, off);
        float rinv = 1.f / sum;
        #pragma unroll
        for (int r = 0; r < 7; r++) {
            int j = lane + 32*r;
            if (j < NTOK) sw[j] = p[r] * rinv;
        }
        __syncwarp();

        float o0 = 0.f, o1 = 0.f;
        for (int j = 0; j < NTOK; j++) {
            float s = sw[j];
            o0 = fmaf(s, Vs[j*64 + lane],      o0);
            o1 = fmaf(s, Vs[j*64 + lane + 32], o1);
        }
        o[((size_t)bt*NTOK + i)*DIMD + hh*DHD + lane]      = __float2half(o0);
        o[((size_t)bt*NTOK + i)*DIMD + hh*DHD + lane + 32] = __float2half(o1);
        __syncwarp();
    }
}

// ---------------- conversions ----------------
__global__ void transpose_f2h(const float* __restrict__ src, __half* __restrict__ dst,
                              int K, int N)
{
    __shared__ float t[32][33];
    size_t lo = (size_t)blockIdx.z * K * N;
    int k0 = blockIdx.y * 32, n0 = blockIdx.x * 32;
    for (int i = threadIdx.y; i < 32; i += 8)
        t[i][threadIdx.x] = src[lo + (size_t)(k0 + i) * N + n0 + threadIdx.x];
    __syncthreads();
    for (int i = threadIdx.y; i < 32; i += 8)
        dst[lo + (size_t)(n0 + i) * K + k0 + threadIdx.x] = __float2half(t[threadIdx.x][i]);
}

__global__ void convert_f2h(const float* __restrict__ src, __half* __restrict__ dst, int n)
{
    int i = blockIdx.x * 256 + threadIdx.x;
    if (i < n) dst[i] = __float2half(src[i]);
}

__global__ void im2col_kernel(const float* __restrict__ img, __half* __restrict__ pv)
{
    int idx = blockIdx.x*256 + threadIdx.x;
    if (idx >= PROWS*DIMD) return;
    int k   = idx % DIMD;
    int row = idx / DIMD;
    int bt = row / NPATCH, p = row % NPATCH;
    int c = k >> 8, rem = k & 255, ii = rem >> 4, jj = rem & 15;
    int ph = p / 14, pw = p % 14;
    pv[idx] = __float2half(img[(((size_t)bt*3 + c)*224 + ph*16 + ii)*224 + pw*16 + jj]);
}

__global__ void assemble_kernel(const float* __restrict__ pe, const float* __restrict__ face,
                                const float* __restrict__ pos, const float* __restrict__ time_emb,
                                const float* __restrict__ cls, float* __restrict__ x)
{
    int idx = blockIdx.x*256 + threadIdx.x;
    if (idx >= ROWS*DIMD) return;
    int n   = idx % DIMD;
    int rem = idx / DIMD;
    int tok = rem % NTOK;
    int bt  = rem / NTOK;
    int t   = bt % 20;
    float v;
    if (tok == 0)           v = cls[n] + pos[n];
    else if (tok <= NPATCH) v = pe[((size_t)bt*NPATCH + tok-1)*DIMD + n] + pos[tok*DIMD + n];
    else                    v = face[((size_t)bt*2 + (tok-197))*DIMD + n];
    x[idx] = v + time_emb[t*DIMD + n];
}

#define OUT_TOT (3*BTT*DIMD + BTT*NPATCH*DIMD)
__global__ void extract_kernel(const float* __restrict__ x, float* __restrict__ out)
{
    int idx = blockIdx.x*256 + threadIdx.x;
    const int P = BTT*DIMD;
    if (idx >= OUT_TOT) return;
    if (idx < 3*P) {
        int part = idx / P;
        int r = idx % P;
        int bt = r / DIMD, n = r % DIMD;
        int tok = (part == 0) ? 0 : (part == 1 ? 197 : 198);
        out[idx] = x[((size_t)bt*NTOK + tok)*DIMD + n];
    } else {
        int r = idx - 3*P;
        int n  = r % DIMD;
        int pp = (r / DIMD) % NPATCH;
        int bt = r / (DIMD*NPATCH);
        out[idx] = x[((size_t)bt*NTOK + 1 + pp)*DIMD + n];
    }
}

// ---------------- host ----------------
static void launch_hgemm(int mode, const __half* A, const __half* B, const float* bias,
                         const float* res, float* C, __half* Ch, int M, int N, int K)
{
    dim3 grid(N/128, (M + 127)/128);
    switch (mode) {
        case 0: hgemm<0><<<grid, 256, GEMM_SMEM>>>(A, B, bias, res, C, Ch, M, N, K); break;
        case 1: hgemm<1><<<grid, 256, GEMM_SMEM>>>(A, B, bias, res, C, Ch, M, N, K); break;
        case 2: hgemm<2><<<grid, 256, GEMM_SMEM>>>(A, B, bias, res, C, Ch, M, N, K); break;
        case 3: hgemm<3><<<grid, 256, GEMM_SMEM>>>(A, B, bias, res, C, Ch, M, N, K); break;
    }
}

extern "C" void kernel_launch(void* const* d_in, const int* in_sizes, int n_in,
                              void* d_out, int out_size)
{
    (void)in_sizes; (void)n_in; (void)out_size;
    const float* img      = (const float*)d_in[0];
    const float* face     = (const float*)d_in[1];
    const float* conv_w   = (const float*)d_in[2];
    const float* conv_b   = (const float*)d_in[3];
    const float* pos_emb  = (const float*)d_in[4];
    const float* time_emb = (const float*)d_in[5];
    const float* cls_tok  = (const float*)d_in[6];
    const float* ln1_s    = (const float*)d_in[7];
    const float* ln1_b    = (const float*)d_in[8];
    const float* qkv_w    = (const float*)d_in[9];
    const float* out_w    = (const float*)d_in[10];
    const float* out_b    = (const float*)d_in[11];
    const float* ln2_s    = (const float*)d_in[12];
    const float* ln2_b    = (const float*)d_in[13];
    const float* ff_w1    = (const float*)d_in[14];
    const float* ff_b1    = (const float*)d_in[15];
    const float* ff_w2    = (const float*)d_in[16];
    const float* ff_b2    = (const float*)d_in[17];
    float* out = (float*)d_out;

    float *gx, *gqkv, *gpe;
    __half *gah, *goh, *gffh, *gwc, *gwqkv, *gwo, *gw1, *gw2;
    cudaGetSymbolAddress((void**)&gx,    g_x);
    cudaGetSymbolAddress((void**)&gqkv,  g_qkv);
    cudaGetSymbolAddress((void**)&gpe,   g_pe);
    cudaGetSymbolAddress((void**)&gah,   g_ah);
    cudaGetSymbolAddress((void**)&goh,   g_oh);
    cudaGetSymbolAddress((void**)&gffh,  g_ffh);
    cudaGetSymbolAddress((void**)&gwc,   g_wc);
    cudaGetSymbolAddress((void**)&gwqkv, g_wqkv);
    cudaGetSymbolAddress((void**)&gwo,   g_wo);
    cudaGetSymbolAddress((void**)&gw1,   g_w1);
    cudaGetSymbolAddress((void**)&gw2,   g_w2);

    cudaFuncSetAttribute(attn_kernel, cudaFuncAttributeMaxDynamicSharedMemorySize, SMEM_ATTN);
    cudaFuncSetAttribute(hgemm<0>, cudaFuncAttributeMaxDynamicSharedMemorySize, GEMM_SMEM);
    cudaFuncSetAttribute(hgemm<1>, cudaFuncAttributeMaxDynamicSharedMemorySize, GEMM_SMEM);
    cudaFuncSetAttribute(hgemm<2>, cudaFuncAttributeMaxDynamicSharedMemorySize, GEMM_SMEM);
    cudaFuncSetAttribute(hgemm<3>, cudaFuncAttributeMaxDynamicSharedMemorySize, GEMM_SMEM);

    // ---- weight conversion (fp32 [K][N] -> fp16 [N][K]) ----
    convert_f2h<<<(DIMD*DIMD + 255)/256, 256>>>(conv_w, gwc, DIMD*DIMD);
    transpose_f2h<<<dim3(3*DIMD/32, DIMD/32, DEPTH), dim3(32,8)>>>(qkv_w, gwqkv, DIMD, 3*DIMD);
    transpose_f2h<<<dim3(DIMD/32, DIMD/32, DEPTH),  dim3(32,8)>>>(out_w, gwo, DIMD, DIMD);
    transpose_f2h<<<dim3(MLPD/32, DIMD/32, DEPTH),  dim3(32,8)>>>(ff_w1, gw1, DIMD, MLPD);
    transpose_f2h<<<dim3(DIMD/32, MLPD/32, DEPTH),  dim3(32,8)>>>(ff_w2, gw2, MLPD, DIMD);

    // ---- patch embed ----
    im2col_kernel<<<(PROWS*DIMD + 255)/256, 256>>>(img, gah);
    launch_hgemm(1, gah, gwc, conv_b, nullptr, gpe, nullptr, PROWS, DIMD, DIMD);
    assemble_kernel<<<(ROWS*DIMD + 255)/256, 256>>>(gpe, face, pos_emb, time_emb, cls_tok, gx);

    // ---- transformer layers ----
    for (int l = 0; l < DEPTH; l++) {
        ln_kernel<<<ROWS, 256>>>(gx, ln1_s + l*DIMD, ln1_b + l*DIMD, gah);
        launch_hgemm(0, gah, gwqkv + (size_t)l*3*DIMD*DIMD, nullptr, nullptr,
                     gqkv, nullptr, ROWS, 3*DIMD, DIMD);
        attn_kernel<<<BTT*HEADS, 256, SMEM_ATTN>>>(gqkv, goh);
        launch_hgemm(2, goh, gwo + (size_t)l*DIMD*DIMD, out_b + l*DIMD, gx,
                     gx, nullptr, ROWS, DIMD, DIMD);
        ln_kernel<<<ROWS, 256>>>(gx, ln2_s + l*DIMD, ln2_b + l*DIMD, gah);
        launch_hgemm(3, gah, gw1 + (size_t)l*MLPD*DIMD, ff_b1 + l*MLPD, nullptr,
                     nullptr, gffh, ROWS, MLPD, DIMD);
        launch_hgemm(2, gffh, gw2 + (size_t)l*DIMD*MLPD, ff_b2 + l*DIMD, gx,
                     gx, nullptr, ROWS, DIMD, MLPD);
    }

    // ---- outputs ----
    extract_kernel<<<(OUT_TOT + 255)/256, 256>>>(gx, out);
}